// round 4
// baseline (speedup 1.0000x reference)
#include <cuda_runtime.h>

#define N 8192
#define F 128
#define ALPHA 0.2f

// ---------------- scratch (static device globals; no allocation) ----------------
__device__ float g_Wh[2][(size_t)N * F];     // Wh per layer
__device__ float g_H [2][(size_t)N * F];     // GAT outputs per layer (normalized)
__device__ float g_f1[2][N], g_f2[2][N];
__device__ float g_E1[2][N], g_E1a[2][N], g_E2[2][N], g_E2a[2][N];
__device__ float g_q[F];
__device__ unsigned int g_layout;                                   // 0=int32, 1=uint8, 2=float32
__device__ unsigned int g_mask[(size_t)2 * N * (N / 32)];           // bit-packed adjacency, 16.8MB

// ---------------- f32x2 helpers ----------------
__device__ __forceinline__ void fma2(unsigned long long& d, unsigned long long a, unsigned long long b) {
    asm("fma.rn.f32x2 %0, %1, %2, %0;" : "+l"(d) : "l"(a), "l"(b));
}
__device__ __forceinline__ unsigned long long pack2(float x) {
    unsigned long long r;
    asm("mov.b64 %0, {%1, %1};" : "=l"(r) : "f"(x));
    return r;
}
__device__ __forceinline__ float2 unpack2(unsigned long long v) {
    float2 r;
    asm("mov.b64 {%0, %1}, %2;" : "=f"(r.x), "=f"(r.y) : "l"(v));
    return r;
}

// ---------------- kernel 0a: detect adjacency element layout ----------------
__global__ void detect_kernel(const unsigned int* __restrict__ adjw) {
    __shared__ unsigned int sHigh, sFloat;
    if (threadIdx.x == 0) { sHigh = 0u; sFloat = 0u; }
    __syncthreads();
    unsigned int hi = 0u, fl = 0u;
    for (int i = threadIdx.x; i < 4096; i += 256) {
        unsigned int w = adjw[i];
        hi |= (w & 0xFFFFFF00u);
        if (w == 0x3F800000u) fl = 1u;
    }
    if (hi) atomicOr(&sHigh, 1u);
    if (fl) atomicOr(&sFloat, 1u);
    __syncthreads();
    if (threadIdx.x == 0) g_layout = sFloat ? 2u : (sHigh ? 1u : 0u);
}

// ---------------- kernel 0b: repack adjacency into bit mask ----------------
__global__ __launch_bounds__(256) void repack_kernel(const void* __restrict__ adj) {
    const size_t w = (size_t)blockIdx.x * 256 + threadIdx.x;  // word index, 32 elems/word
    const unsigned int layout = g_layout;
    unsigned int bits = 0u;
    if (layout == 1u) {
        // uint8 layout: 32 bytes = 2 x uint4
        const uint4* p = (const uint4*)adj + w * 2;
        uint4 x0 = p[0], x1 = p[1];
        unsigned int v[8] = {x0.x, x0.y, x0.z, x0.w, x1.x, x1.y, x1.z, x1.w};
#pragma unroll
        for (int j = 0; j < 8; j++)
#pragma unroll
            for (int k = 0; k < 4; k++)
                bits |= (((v[j] >> (8 * k)) & 1u) != 0u ? 1u : 0u) << (j * 4 + k);
    } else {
        // int32 or float32 layout: 32 x 4-byte elems = 8 x uint4; nonzero bits => true
        const uint4* p = (const uint4*)adj + w * 8;
#pragma unroll
        for (int j = 0; j < 8; j++) {
            uint4 x = p[j];
            bits |= (x.x != 0u ? 1u : 0u) << (j * 4 + 0);
            bits |= (x.y != 0u ? 1u : 0u) << (j * 4 + 1);
            bits |= (x.z != 0u ? 1u : 0u) << (j * 4 + 2);
            bits |= (x.w != 0u ? 1u : 0u) << (j * 4 + 3);
        }
    }
    g_mask[w] = bits;
}

// ---------------- kernel 1: Wh = X @ W (both layers) ----------------
__global__ __launch_bounds__(256) void wh_kernel(const float* __restrict__ X,
                                                 const float* __restrict__ W0,
                                                 const float* __restrict__ W1) {
    const int layer = blockIdx.y;
    const float* Xl = X + (size_t)layer * N * F;
    const float* W  = layer ? W1 : W0;
    float* out = g_Wh[layer];
    const int i0 = blockIdx.x * 64;

    __shared__ float Xs[64][33];
    __shared__ __align__(16) float Ws[32][128];

    const int tid = threadIdx.x;
    const int tx = tid & 15;   // feature group: 8 features
    const int ty = tid >> 4;   // row group: 4 rows

    float acc[4][8];
#pragma unroll
    for (int r = 0; r < 4; r++)
#pragma unroll
        for (int c = 0; c < 8; c++) acc[r][c] = 0.f;

    for (int k0 = 0; k0 < F; k0 += 32) {
        for (int idx = tid; idx < 64 * 32; idx += 256) {
            int r = idx >> 5, kk = idx & 31;
            Xs[r][kk] = Xl[(size_t)(i0 + r) * F + k0 + kk];
        }
        for (int idx = tid; idx < 32 * 32; idx += 256) {
            int kk = idx >> 5, f4 = idx & 31;
            *(float4*)&Ws[kk][f4 * 4] = *(const float4*)&W[(size_t)(k0 + kk) * F + f4 * 4];
        }
        __syncthreads();
#pragma unroll 8
        for (int kk = 0; kk < 32; kk++) {
            float xv[4], wv[8];
#pragma unroll
            for (int r = 0; r < 4; r++) xv[r] = Xs[ty * 4 + r][kk];
#pragma unroll
            for (int c = 0; c < 8; c++) wv[c] = Ws[kk][tx * 8 + c];
#pragma unroll
            for (int r = 0; r < 4; r++)
#pragma unroll
                for (int c = 0; c < 8; c++) acc[r][c] = fmaf(xv[r], wv[c], acc[r][c]);
        }
        __syncthreads();
    }
#pragma unroll
    for (int r = 0; r < 4; r++) {
        int row = i0 + ty * 4 + r;
        float4 o0 = make_float4(acc[r][0], acc[r][1], acc[r][2], acc[r][3]);
        float4 o1 = make_float4(acc[r][4], acc[r][5], acc[r][6], acc[r][7]);
        *(float4*)&out[(size_t)row * F + tx * 8]     = o0;
        *(float4*)&out[(size_t)row * F + tx * 8 + 4] = o1;
    }
}

// ---------------- kernel 2: f1/f2 and exp tables ----------------
__global__ __launch_bounds__(256) void fe_kernel(const float* __restrict__ a0,
                                                 const float* __restrict__ a1) {
    const int layer = blockIdx.y;
    const float* a = layer ? a1 : a0;
    const int warp = threadIdx.x >> 5, lane = threadIdx.x & 31;
    const int i = blockIdx.x * 8 + warp;
    const float* wh = &g_Wh[layer][(size_t)i * F];

    float s1 = 0.f, s2 = 0.f;
#pragma unroll
    for (int m = 0; m < 4; m++) {
        int f = lane + 32 * m;
        float v = wh[f];
        s1 = fmaf(v, a[f], s1);
        s2 = fmaf(v, a[F + f], s2);
    }
#pragma unroll
    for (int o = 16; o; o >>= 1) {
        s1 += __shfl_xor_sync(0xffffffffu, s1, o);
        s2 += __shfl_xor_sync(0xffffffffu, s2, o);
    }
    if (lane == 0) {
        g_f1 [layer][i] = s1;
        g_f2 [layer][i] = s2;
        g_E1 [layer][i] = expf(s1);
        g_E1a[layer][i] = expf(ALPHA * s1);
        g_E2 [layer][i] = expf(s2);
        g_E2a[layer][i] = expf(ALPHA * s2);
    }
}

// ---------------- kernel 3: fused masked-softmax attention + P@Wh ----------------
// Block: 128 rows x all 8192 cols, 256 threads, TJ=32 column tiles.
__global__ __launch_bounds__(256) void attn_kernel() {
    const int layer = blockIdx.y;
    const int i0 = blockIdx.x * 128;
    const unsigned int* mk = g_mask + (size_t)layer * N * (N / 32);
    const float* Wh = g_Wh[layer];
    float* H = g_H[layer];

    __shared__ float Ps[32][129];                    // P tile, transposed, padded (conflict-free)
    __shared__ __align__(16) float Whs[32][128];     // Wh tile
    __shared__ float f1s[128], E1s[128], E1as[128], Zs[128];
    __shared__ float f2s[32], E2s[32], E2as[32];

    const int tid = threadIdx.x;
    const int lane = tid & 31, warp = tid >> 5;
    const int tx = tid & 15;   // feature group: tx*8 .. +7
    const int ty = tid >> 4;   // row group: ty*8 .. +7

    if (tid < 128) {
        f1s [tid] = g_f1 [layer][i0 + tid];
        E1s [tid] = g_E1 [layer][i0 + tid];
        E1as[tid] = g_E1a[layer][i0 + tid];
        Zs  [tid] = 0.f;
    }

    unsigned long long acc[8][4];
#pragma unroll
    for (int r = 0; r < 8; r++)
#pragma unroll
        for (int q = 0; q < 4; q++) acc[r][q] = 0ull;

    for (int j0 = 0; j0 < N; j0 += 32) {
        // load Wh tile (coalesced float4)
#pragma unroll
        for (int k = 0; k < 4; k++) {
            int f4 = tid + k * 256;
            int jj = f4 >> 5, fo = (f4 & 31) << 2;
            *(float4*)&Whs[jj][fo] = *(const float4*)&Wh[(size_t)(j0 + jj) * F + fo];
        }
        if (tid < 32) {
            f2s [tid] = g_f2 [layer][j0 + tid];
            E2s [tid] = g_E2 [layer][j0 + tid];
            E2as[tid] = g_E2a[layer][j0 + tid];
        }
        __syncthreads();

        // P-tile generation: warp handles rows [warp*16, warp*16+16)
#pragma unroll
        for (int rr = 0; rr < 4; rr++) {
            int r  = warp * 16 + rr * 4 + (lane >> 3);
            int jb = (lane & 7) * 4;
            unsigned int mword = mk[(size_t)(i0 + r) * (N / 32) + (j0 >> 5)];
            float f1 = f1s[r], e1 = E1s[r], e1a = E1as[r];
            float zp = 0.f;
#pragma unroll
            for (int c = 0; c < 4; c++) {
                int jj = jb + c;
                float t = f1 + f2s[jj];
                float p = (t > 0.f) ? e1 * E2s[jj] : e1a * E2as[jj];
                p = ((mword >> jj) & 1u) ? p : 0.f;
                Ps[jj][r] = p;
                zp += p;
            }
            zp += __shfl_xor_sync(0xffffffffu, zp, 1);
            zp += __shfl_xor_sync(0xffffffffu, zp, 2);
            zp += __shfl_xor_sync(0xffffffffu, zp, 4);
            if ((lane & 7) == 0) Zs[r] += zp;
        }
        __syncthreads();

        // GEMM: O[128,128] += P^T-tile @ Wh-tile, f32x2 packed FFMA
#pragma unroll 8
        for (int jj = 0; jj < 32; jj++) {
            ulonglong2 wA = *(const ulonglong2*)&Whs[jj][tx * 8];
            ulonglong2 wB = *(const ulonglong2*)&Whs[jj][tx * 8 + 4];
#pragma unroll
            for (int r = 0; r < 8; r++) {
                unsigned long long pp = pack2(Ps[jj][ty * 8 + r]);
                fma2(acc[r][0], pp, wA.x);
                fma2(acc[r][1], pp, wA.y);
                fma2(acc[r][2], pp, wB.x);
                fma2(acc[r][3], pp, wB.y);
            }
        }
        __syncthreads();
    }

    // epilogue: normalize by row-sum Z and store
#pragma unroll
    for (int r = 0; r < 8; r++) {
        int row = ty * 8 + r;
        float inv = 1.f / Zs[row];
        float2 a0v = unpack2(acc[r][0]);
        float2 a1v = unpack2(acc[r][1]);
        float2 a2v = unpack2(acc[r][2]);
        float2 a3v = unpack2(acc[r][3]);
        float4 o0 = make_float4(a0v.x * inv, a0v.y * inv, a1v.x * inv, a1v.y * inv);
        float4 o1 = make_float4(a2v.x * inv, a2v.y * inv, a3v.x * inv, a3v.y * inv);
        *(float4*)&H[(size_t)(i0 + row) * F + tx * 8]     = o0;
        *(float4*)&H[(size_t)(i0 + row) * F + tx * 8 + 4] = o1;
    }
}

// ---------------- kernel 4: layernorm(query) -> g_q ----------------
__global__ void qnorm_kernel(const float* __restrict__ query,
                             const float* __restrict__ gamma,
                             const float* __restrict__ beta) {
    __shared__ float red[4];
    const int t = threadIdx.x;  // 128 threads
    float x = query[t];
    float s = x;
#pragma unroll
    for (int o = 16; o; o >>= 1) s += __shfl_xor_sync(0xffffffffu, s, o);
    if ((t & 31) == 0) red[t >> 5] = s;
    __syncthreads();
    float mu = (red[0] + red[1] + red[2] + red[3]) * (1.f / 128.f);
    float d = x - mu;
    float v = d * d;
    __syncthreads();
#pragma unroll
    for (int o = 16; o; o >>= 1) v += __shfl_xor_sync(0xffffffffu, v, o);
    if ((t & 31) == 0) red[t >> 5] = v;
    __syncthreads();
    float var = (red[0] + red[1] + red[2] + red[3]) * (1.f / 128.f);
    g_q[t] = d * rsqrtf(var + 1e-5f) * gamma[t] + beta[t];
}

// ---------------- kernel 5: score softmax + mix + residual ----------------
__global__ __launch_bounds__(256) void mix_kernel(const float* __restrict__ input_hs,
                                                  const float* __restrict__ M,
                                                  const float* __restrict__ resp,
                                                  float* __restrict__ out) {
    const int warp = threadIdx.x >> 5, lane = threadIdx.x & 31;
    const int i = blockIdx.x * 8 + warp;
    const float* h0 = &g_H[0][(size_t)i * F];
    const float* h1 = &g_H[1][(size_t)i * F];
    const float* mm = &M[(size_t)i * F];
    const float* x0 = &input_hs[(size_t)i * F];

    float h0v[4], h1v[4], mv[4];
    float d0 = 0.f, d1 = 0.f, d2 = 0.f;
#pragma unroll
    for (int m = 0; m < 4; m++) {
        int f = lane + 32 * m;
        h0v[m] = h0[f];
        h1v[m] = h1[f];
        mv[m]  = mm[f];
        float q = g_q[f];
        d0 = fmaf(h0v[m], q, d0);
        d1 = fmaf(h1v[m], q, d1);
        d2 = fmaf(mv[m],  q, d2);
    }
#pragma unroll
    for (int o = 16; o; o >>= 1) {
        d0 += __shfl_xor_sync(0xffffffffu, d0, o);
        d1 += __shfl_xor_sync(0xffffffffu, d1, o);
        d2 += __shfl_xor_sync(0xffffffffu, d2, o);
    }
    float mx = fmaxf(d0, fmaxf(d1, d2));
    float e0 = expf(d0 - mx), e1 = expf(d1 - mx), e2 = expf(d2 - mx);
    float inv = 1.f / (e0 + e1 + e2);
    float s0 = e0 * inv, s1 = e1 * inv, s2 = e2 * inv;
    float r = resp[0];
#pragma unroll
    for (int m = 0; m < 4; m++) {
        int f = lane + 32 * m;
        out[(size_t)i * F + f] = fmaf(r, s0 * h0v[m] + s1 * h1v[m] + s2 * mv[m], x0[f]);
    }
}

// ---------------- launcher ----------------
extern "C" void kernel_launch(void* const* d_in, const int* in_sizes, int n_in,
                              void* d_out, int out_size) {
    const float* input_hs = (const float*)d_in[0];
    const void*  adjs     = d_in[1];
    const float* MPNN     = (const float*)d_in[2];
    const float* query    = (const float*)d_in[3];
    const float* W0       = (const float*)d_in[4];
    const float* a0       = (const float*)d_in[5];
    const float* W1       = (const float*)d_in[6];
    const float* a1       = (const float*)d_in[7];
    const float* gamma    = (const float*)d_in[8];
    const float* beta     = (const float*)d_in[9];
    const float* res      = (const float*)d_in[10];
    float* out = (float*)d_out;

    detect_kernel<<<1, 256>>>((const unsigned int*)adjs);
    repack_kernel<<<(2 * (size_t)N * N / 32) / 256, 256>>>(adjs);
    wh_kernel  <<<dim3(N / 64, 2), 256>>>(input_hs, W0, W1);
    fe_kernel  <<<dim3(N / 8, 2), 256>>>(a0, a1);
    attn_kernel<<<dim3(N / 128, 2), 256>>>();
    qnorm_kernel<<<1, 128>>>(query, gamma, beta);
    mix_kernel <<<N / 8, 256>>>(input_hs, MPNN, res, out);
}

// round 9
// speedup vs baseline: 1.0044x; 1.0044x over previous
#include <cuda_runtime.h>

#define N 8192
#define F 128
#define ALPHA 0.2f

// ---------------- scratch (static device globals; no allocation) ----------------
__device__ float g_Wh[2][(size_t)N * F];     // Wh per layer
__device__ float g_H [2][(size_t)N * F];     // GAT outputs per layer (normalized)
__device__ float g_f1[2][N], g_f2[2][N];
__device__ float g_E1[2][N], g_E1a[2][N], g_E2[2][N], g_E2a[2][N];
__device__ float g_q[F];
__device__ unsigned int g_layout;                                   // 0=int32, 1=uint8, 2=float32
__device__ unsigned int g_mask[(size_t)2 * N * (N / 32)];           // bit-packed adjacency, 16.8MB

// ---------------- f32x2 helpers ----------------
__device__ __forceinline__ void fma2(unsigned long long& d, unsigned long long a, unsigned long long b) {
    asm("fma.rn.f32x2 %0, %1, %2, %0;" : "+l"(d) : "l"(a), "l"(b));
}
__device__ __forceinline__ unsigned long long pack2(float x) {
    unsigned long long r;
    asm("mov.b64 %0, {%1, %1};" : "=l"(r) : "f"(x));
    return r;
}
__device__ __forceinline__ float2 unpack2(unsigned long long v) {
    float2 r;
    asm("mov.b64 {%0, %1}, %2;" : "=f"(r.x), "=f"(r.y) : "l"(v));
    return r;
}

// ---------------- kernel 0a: detect adjacency element layout ----------------
__global__ void detect_kernel(const unsigned int* __restrict__ adjw) {
    __shared__ unsigned int sHigh, sFloat;
    if (threadIdx.x == 0) { sHigh = 0u; sFloat = 0u; }
    __syncthreads();
    unsigned int hi = 0u, fl = 0u;
    for (int i = threadIdx.x; i < 4096; i += 256) {
        unsigned int w = adjw[i];
        hi |= (w & 0xFFFFFF00u);
        if (w == 0x3F800000u) fl = 1u;
    }
    if (hi) atomicOr(&sHigh, 1u);
    if (fl) atomicOr(&sFloat, 1u);
    __syncthreads();
    if (threadIdx.x == 0) g_layout = sFloat ? 2u : (sHigh ? 1u : 0u);
}

// ---------------- kernel 0b: repack adjacency into bit mask ----------------
__global__ __launch_bounds__(256) void repack_kernel(const void* __restrict__ adj) {
    const size_t w = (size_t)blockIdx.x * 256 + threadIdx.x;  // word index, 32 elems/word
    const unsigned int layout = g_layout;
    unsigned int bits = 0u;
    if (layout == 1u) {
        // uint8 layout: 32 bytes = 2 x uint4
        const uint4* p = (const uint4*)adj + w * 2;
        uint4 x0 = p[0], x1 = p[1];
        unsigned int v[8] = {x0.x, x0.y, x0.z, x0.w, x1.x, x1.y, x1.z, x1.w};
#pragma unroll
        for (int j = 0; j < 8; j++)
#pragma unroll
            for (int k = 0; k < 4; k++)
                bits |= (((v[j] >> (8 * k)) & 1u) != 0u ? 1u : 0u) << (j * 4 + k);
    } else {
        // int32 or float32 layout: 32 x 4-byte elems = 8 x uint4; nonzero bits => true
        const uint4* p = (const uint4*)adj + w * 8;
#pragma unroll
        for (int j = 0; j < 8; j++) {
            uint4 x = p[j];
            bits |= (x.x != 0u ? 1u : 0u) << (j * 4 + 0);
            bits |= (x.y != 0u ? 1u : 0u) << (j * 4 + 1);
            bits |= (x.z != 0u ? 1u : 0u) << (j * 4 + 2);
            bits |= (x.w != 0u ? 1u : 0u) << (j * 4 + 3);
        }
    }
    g_mask[w] = bits;
}

// ---------------- kernel 1: Wh = X @ W (both layers) ----------------
__global__ __launch_bounds__(256) void wh_kernel(const float* __restrict__ X,
                                                 const float* __restrict__ W0,
                                                 const float* __restrict__ W1) {
    const int layer = blockIdx.y;
    const float* Xl = X + (size_t)layer * N * F;
    const float* W  = layer ? W1 : W0;
    float* out = g_Wh[layer];
    const int i0 = blockIdx.x * 64;

    __shared__ float Xs[64][33];
    __shared__ __align__(16) float Ws[32][128];

    const int tid = threadIdx.x;
    const int tx = tid & 15;   // feature group: 8 features
    const int ty = tid >> 4;   // row group: 4 rows

    float acc[4][8];
#pragma unroll
    for (int r = 0; r < 4; r++)
#pragma unroll
        for (int c = 0; c < 8; c++) acc[r][c] = 0.f;

    for (int k0 = 0; k0 < F; k0 += 32) {
        for (int idx = tid; idx < 64 * 32; idx += 256) {
            int r = idx >> 5, kk = idx & 31;
            Xs[r][kk] = Xl[(size_t)(i0 + r) * F + k0 + kk];
        }
        for (int idx = tid; idx < 32 * 32; idx += 256) {
            int kk = idx >> 5, f4 = idx & 31;
            *(float4*)&Ws[kk][f4 * 4] = *(const float4*)&W[(size_t)(k0 + kk) * F + f4 * 4];
        }
        __syncthreads();
#pragma unroll 8
        for (int kk = 0; kk < 32; kk++) {
            float xv[4], wv[8];
#pragma unroll
            for (int r = 0; r < 4; r++) xv[r] = Xs[ty * 4 + r][kk];
#pragma unroll
            for (int c = 0; c < 8; c++) wv[c] = Ws[kk][tx * 8 + c];
#pragma unroll
            for (int r = 0; r < 4; r++)
#pragma unroll
                for (int c = 0; c < 8; c++) acc[r][c] = fmaf(xv[r], wv[c], acc[r][c]);
        }
        __syncthreads();
    }
#pragma unroll
    for (int r = 0; r < 4; r++) {
        int row = i0 + ty * 4 + r;
        float4 o0 = make_float4(acc[r][0], acc[r][1], acc[r][2], acc[r][3]);
        float4 o1 = make_float4(acc[r][4], acc[r][5], acc[r][6], acc[r][7]);
        *(float4*)&out[(size_t)row * F + tx * 8]     = o0;
        *(float4*)&out[(size_t)row * F + tx * 8 + 4] = o1;
    }
}

// ---------------- kernel 2: f1/f2 and exp tables ----------------
__global__ __launch_bounds__(256) void fe_kernel(const float* __restrict__ a0,
                                                 const float* __restrict__ a1) {
    const int layer = blockIdx.y;
    const float* a = layer ? a1 : a0;
    const int warp = threadIdx.x >> 5, lane = threadIdx.x & 31;
    const int i = blockIdx.x * 8 + warp;
    const float* wh = &g_Wh[layer][(size_t)i * F];

    float s1 = 0.f, s2 = 0.f;
#pragma unroll
    for (int m = 0; m < 4; m++) {
        int f = lane + 32 * m;
        float v = wh[f];
        s1 = fmaf(v, a[f], s1);
        s2 = fmaf(v, a[F + f], s2);
    }
#pragma unroll
    for (int o = 16; o; o >>= 1) {
        s1 += __shfl_xor_sync(0xffffffffu, s1, o);
        s2 += __shfl_xor_sync(0xffffffffu, s2, o);
    }
    if (lane == 0) {
        g_f1 [layer][i] = s1;
        g_f2 [layer][i] = s2;
        g_E1 [layer][i] = expf(s1);
        g_E1a[layer][i] = expf(ALPHA * s1);
        g_E2 [layer][i] = expf(s2);
        g_E2a[layer][i] = expf(ALPHA * s2);
    }
}

// ---------------- kernel 3: fused masked-softmax attention + P@Wh ----------------
// Block: 128 rows x all 8192 cols, 256 threads, TJ=32 column tiles.
__global__ __launch_bounds__(256) void attn_kernel() {
    const int layer = blockIdx.y;
    const int i0 = blockIdx.x * 128;
    const unsigned int* mk = g_mask + (size_t)layer * N * (N / 32);
    const float* Wh = g_Wh[layer];
    float* H = g_H[layer];

    __shared__ float Ps[32][129];                    // P tile, transposed, padded (conflict-free)
    __shared__ __align__(16) float Whs[32][128];     // Wh tile
    __shared__ float f1s[128], E1s[128], E1as[128], Zs[128];
    __shared__ float f2s[32], E2s[32], E2as[32];

    const int tid = threadIdx.x;
    const int lane = tid & 31, warp = tid >> 5;
    const int tx = tid & 15;   // feature group: tx*8 .. +7
    const int ty = tid >> 4;   // row group: ty*8 .. +7

    if (tid < 128) {
        f1s [tid] = g_f1 [layer][i0 + tid];
        E1s [tid] = g_E1 [layer][i0 + tid];
        E1as[tid] = g_E1a[layer][i0 + tid];
        Zs  [tid] = 0.f;
    }

    unsigned long long acc[8][4];
#pragma unroll
    for (int r = 0; r < 8; r++)
#pragma unroll
        for (int q = 0; q < 4; q++) acc[r][q] = 0ull;

    for (int j0 = 0; j0 < N; j0 += 32) {
        // load Wh tile (coalesced float4)
#pragma unroll
        for (int k = 0; k < 4; k++) {
            int f4 = tid + k * 256;
            int jj = f4 >> 5, fo = (f4 & 31) << 2;
            *(float4*)&Whs[jj][fo] = *(const float4*)&Wh[(size_t)(j0 + jj) * F + fo];
        }
        if (tid < 32) {
            f2s [tid] = g_f2 [layer][j0 + tid];
            E2s [tid] = g_E2 [layer][j0 + tid];
            E2as[tid] = g_E2a[layer][j0 + tid];
        }
        __syncthreads();

        // P-tile generation: warp handles rows [warp*16, warp*16+16)
#pragma unroll
        for (int rr = 0; rr < 4; rr++) {
            int r  = warp * 16 + rr * 4 + (lane >> 3);
            int jb = (lane & 7) * 4;
            unsigned int mword = mk[(size_t)(i0 + r) * (N / 32) + (j0 >> 5)];
            float f1 = f1s[r], e1 = E1s[r], e1a = E1as[r];
            float zp = 0.f;
#pragma unroll
            for (int c = 0; c < 4; c++) {
                int jj = jb + c;
                float t = f1 + f2s[jj];
                float p = (t > 0.f) ? e1 * E2s[jj] : e1a * E2as[jj];
                p = ((mword >> jj) & 1u) ? p : 0.f;
                Ps[jj][r] = p;
                zp += p;
            }
            zp += __shfl_xor_sync(0xffffffffu, zp, 1);
            zp += __shfl_xor_sync(0xffffffffu, zp, 2);
            zp += __shfl_xor_sync(0xffffffffu, zp, 4);
            if ((lane & 7) == 0) Zs[r] += zp;
        }
        __syncthreads();

        // GEMM: O[128,128] += P^T-tile @ Wh-tile, f32x2 packed FFMA
#pragma unroll 8
        for (int jj = 0; jj < 32; jj++) {
            ulonglong2 wA = *(const ulonglong2*)&Whs[jj][tx * 8];
            ulonglong2 wB = *(const ulonglong2*)&Whs[jj][tx * 8 + 4];
#pragma unroll
            for (int r = 0; r < 8; r++) {
                unsigned long long pp = pack2(Ps[jj][ty * 8 + r]);
                fma2(acc[r][0], pp, wA.x);
                fma2(acc[r][1], pp, wA.y);
                fma2(acc[r][2], pp, wB.x);
                fma2(acc[r][3], pp, wB.y);
            }
        }
        __syncthreads();
    }

    // epilogue: normalize by row-sum Z and store
#pragma unroll
    for (int r = 0; r < 8; r++) {
        int row = ty * 8 + r;
        float inv = 1.f / Zs[row];
        float2 a0v = unpack2(acc[r][0]);
        float2 a1v = unpack2(acc[r][1]);
        float2 a2v = unpack2(acc[r][2]);
        float2 a3v = unpack2(acc[r][3]);
        float4 o0 = make_float4(a0v.x * inv, a0v.y * inv, a1v.x * inv, a1v.y * inv);
        float4 o1 = make_float4(a2v.x * inv, a2v.y * inv, a3v.x * inv, a3v.y * inv);
        *(float4*)&H[(size_t)(i0 + row) * F + tx * 8]     = o0;
        *(float4*)&H[(size_t)(i0 + row) * F + tx * 8 + 4] = o1;
    }
}

// ---------------- kernel 4: layernorm(query) -> g_q ----------------
__global__ void qnorm_kernel(const float* __restrict__ query,
                             const float* __restrict__ gamma,
                             const float* __restrict__ beta) {
    __shared__ float red[4];
    const int t = threadIdx.x;  // 128 threads
    float x = query[t];
    float s = x;
#pragma unroll
    for (int o = 16; o; o >>= 1) s += __shfl_xor_sync(0xffffffffu, s, o);
    if ((t & 31) == 0) red[t >> 5] = s;
    __syncthreads();
    float mu = (red[0] + red[1] + red[2] + red[3]) * (1.f / 128.f);
    float d = x - mu;
    float v = d * d;
    __syncthreads();
#pragma unroll
    for (int o = 16; o; o >>= 1) v += __shfl_xor_sync(0xffffffffu, v, o);
    if ((t & 31) == 0) red[t >> 5] = v;
    __syncthreads();
    float var = (red[0] + red[1] + red[2] + red[3]) * (1.f / 128.f);
    g_q[t] = d * rsqrtf(var + 1e-5f) * gamma[t] + beta[t];
}

// ---------------- kernel 5: score softmax + mix + residual ----------------
__global__ __launch_bounds__(256) void mix_kernel(const float* __restrict__ input_hs,
                                                  const float* __restrict__ M,
                                                  const float* __restrict__ resp,
                                                  float* __restrict__ out) {
    const int warp = threadIdx.x >> 5, lane = threadIdx.x & 31;
    const int i = blockIdx.x * 8 + warp;
    const float* h0 = &g_H[0][(size_t)i * F];
    const float* h1 = &g_H[1][(size_t)i * F];
    const float* mm = &M[(size_t)i * F];
    const float* x0 = &input_hs[(size_t)i * F];

    float h0v[4], h1v[4], mv[4];
    float d0 = 0.f, d1 = 0.f, d2 = 0.f;
#pragma unroll
    for (int m = 0; m < 4; m++) {
        int f = lane + 32 * m;
        h0v[m] = h0[f];
        h1v[m] = h1[f];
        mv[m]  = mm[f];
        float q = g_q[f];
        d0 = fmaf(h0v[m], q, d0);
        d1 = fmaf(h1v[m], q, d1);
        d2 = fmaf(mv[m],  q, d2);
    }
#pragma unroll
    for (int o = 16; o; o >>= 1) {
        d0 += __shfl_xor_sync(0xffffffffu, d0, o);
        d1 += __shfl_xor_sync(0xffffffffu, d1, o);
        d2 += __shfl_xor_sync(0xffffffffu, d2, o);
    }
    float mx = fmaxf(d0, fmaxf(d1, d2));
    float e0 = expf(d0 - mx), e1 = expf(d1 - mx), e2 = expf(d2 - mx);
    float inv = 1.f / (e0 + e1 + e2);
    float s0 = e0 * inv, s1 = e1 * inv, s2 = e2 * inv;
    float r = resp[0];
#pragma unroll
    for (int m = 0; m < 4; m++) {
        int f = lane + 32 * m;
        out[(size_t)i * F + f] = fmaf(r, s0 * h0v[m] + s1 * h1v[m] + s2 * mv[m], x0[f]);
    }
}

// ---------------- launcher ----------------
extern "C" void kernel_launch(void* const* d_in, const int* in_sizes, int n_in,
                              void* d_out, int out_size) {
    const float* input_hs = (const float*)d_in[0];
    const void*  adjs     = d_in[1];
    const float* MPNN     = (const float*)d_in[2];
    const float* query    = (const float*)d_in[3];
    const float* W0       = (const float*)d_in[4];
    const float* a0       = (const float*)d_in[5];
    const float* W1       = (const float*)d_in[6];
    const float* a1       = (const float*)d_in[7];
    const float* gamma    = (const float*)d_in[8];
    const float* beta     = (const float*)d_in[9];
    const float* res      = (const float*)d_in[10];
    float* out = (float*)d_out;

    detect_kernel<<<1, 256>>>((const unsigned int*)adjs);
    repack_kernel<<<(2 * (size_t)N * N / 32) / 256, 256>>>(adjs);
    wh_kernel  <<<dim3(N / 64, 2), 256>>>(input_hs, W0, W1);
    fe_kernel  <<<dim3(N / 8, 2), 256>>>(a0, a1);
    attn_kernel<<<dim3(N / 128, 2), 256>>>();
    qnorm_kernel<<<1, 128>>>(query, gamma, beta);
    mix_kernel <<<N / 8, 256>>>(input_hs, MPNN, res, out);
}

// round 11
// speedup vs baseline: 3.7837x; 3.7669x over previous
#include <cuda_runtime.h>
#include <cuda_bf16.h>
#include <cstdint>

#define N 8192
#define F 128
#define ALPHA 0.2f
#define CHUNK 1024

// ---------------- scratch (static device globals; no allocation) ----------------
__device__ float g_Wh[2][(size_t)N * F];
__device__ float g_H [2][(size_t)N * F];
__device__ float g_f1[2][N], g_f2[2][N];
__device__ float g_E1[2][N], g_E1a[2][N], g_E2[2][N], g_E2a[2][N];
__device__ float g_q[F];
__device__ unsigned int g_layout;                                   // 0=int32, 1=uint8, 2=float32
__device__ unsigned int g_mask[(size_t)2 * N * (N / 32)];           // bit-packed adjacency
// B fragments for mma.m16n8k16, pre-packed: [layer][kstep(512)][fpair(16)][lane(32)] uint4
__device__ uint4 g_Bfrag[(size_t)2 * 512 * 16 * 32];

// ---------------- helpers ----------------
__device__ __forceinline__ uint32_t bf16pk(float lo, float hi) {
    uint32_t r;
    asm("cvt.rn.bf16x2.f32 %0, %1, %2;" : "=r"(r) : "f"(hi), "f"(lo));
    return r;
}
__device__ __forceinline__ void mma16816(float* d, const uint32_t* a, const uint32_t* b) {
    asm volatile(
        "mma.sync.aligned.m16n8k16.row.col.f32.bf16.bf16.f32 "
        "{%0,%1,%2,%3}, {%4,%5,%6,%7}, {%8,%9}, {%0,%1,%2,%3};"
        : "+f"(d[0]), "+f"(d[1]), "+f"(d[2]), "+f"(d[3])
        : "r"(a[0]), "r"(a[1]), "r"(a[2]), "r"(a[3]), "r"(b[0]), "r"(b[1]));
}
__device__ __forceinline__ float pval(float f1, float e1, float e1a,
                                      const float4 T, unsigned int mw, int bit) {
    float t = f1 + T.x;
    float p = (t > 0.f) ? e1 * T.y : e1a * T.z;
    return ((mw >> bit) & 1u) ? p : 0.f;
}

// ---------------- kernel 0a: detect adjacency element layout ----------------
__global__ void detect_kernel(const unsigned int* __restrict__ adjw) {
    __shared__ unsigned int sHigh, sFloat;
    if (threadIdx.x == 0) { sHigh = 0u; sFloat = 0u; }
    __syncthreads();
    unsigned int hi = 0u, fl = 0u;
    for (int i = threadIdx.x; i < 4096; i += 256) {
        unsigned int w = adjw[i];
        hi |= (w & 0xFFFFFF00u);
        if (w == 0x3F800000u) fl = 1u;
    }
    if (hi) atomicOr(&sHigh, 1u);
    if (fl) atomicOr(&sFloat, 1u);
    __syncthreads();
    if (threadIdx.x == 0) g_layout = sFloat ? 2u : (sHigh ? 1u : 0u);
}

// ---------------- kernel 0b: repack adjacency into bit mask ----------------
__global__ __launch_bounds__(256) void repack_kernel(const void* __restrict__ adj) {
    const size_t w = (size_t)blockIdx.x * 256 + threadIdx.x;
    const unsigned int layout = g_layout;
    unsigned int bits = 0u;
    if (layout == 1u) {
        const uint4* p = (const uint4*)adj + w * 2;
        uint4 x0 = p[0], x1 = p[1];
        unsigned int v[8] = {x0.x, x0.y, x0.z, x0.w, x1.x, x1.y, x1.z, x1.w};
#pragma unroll
        for (int j = 0; j < 8; j++)
#pragma unroll
            for (int k = 0; k < 4; k++)
                bits |= (((v[j] >> (8 * k)) & 0xFFu) != 0u ? 1u : 0u) << (j * 4 + k);
    } else {
        const uint4* p = (const uint4*)adj + w * 8;
#pragma unroll
        for (int j = 0; j < 8; j++) {
            uint4 x = p[j];
            bits |= (x.x != 0u ? 1u : 0u) << (j * 4 + 0);
            bits |= (x.y != 0u ? 1u : 0u) << (j * 4 + 1);
            bits |= (x.z != 0u ? 1u : 0u) << (j * 4 + 2);
            bits |= (x.w != 0u ? 1u : 0u) << (j * 4 + 3);
        }
    }
    g_mask[w] = bits;
}

// ---------------- kernel 1: Wh = X @ W (both layers) ----------------
__global__ __launch_bounds__(256) void wh_kernel(const float* __restrict__ X,
                                                 const float* __restrict__ W0,
                                                 const float* __restrict__ W1) {
    const int layer = blockIdx.y;
    const float* Xl = X + (size_t)layer * N * F;
    const float* W  = layer ? W1 : W0;
    float* out = g_Wh[layer];
    const int i0 = blockIdx.x * 64;

    __shared__ float Xs[64][33];
    __shared__ __align__(16) float Ws[32][128];

    const int tid = threadIdx.x;
    const int tx = tid & 15;
    const int ty = tid >> 4;

    float acc[4][8];
#pragma unroll
    for (int r = 0; r < 4; r++)
#pragma unroll
        for (int c = 0; c < 8; c++) acc[r][c] = 0.f;

    for (int k0 = 0; k0 < F; k0 += 32) {
        for (int idx = tid; idx < 64 * 32; idx += 256) {
            int r = idx >> 5, kk = idx & 31;
            Xs[r][kk] = Xl[(size_t)(i0 + r) * F + k0 + kk];
        }
        for (int idx = tid; idx < 32 * 32; idx += 256) {
            int kk = idx >> 5, f4 = idx & 31;
            *(float4*)&Ws[kk][f4 * 4] = *(const float4*)&W[(size_t)(k0 + kk) * F + f4 * 4];
        }
        __syncthreads();
#pragma unroll 8
        for (int kk = 0; kk < 32; kk++) {
            float xv[4], wv[8];
#pragma unroll
            for (int r = 0; r < 4; r++) xv[r] = Xs[ty * 4 + r][kk];
#pragma unroll
            for (int c = 0; c < 8; c++) wv[c] = Ws[kk][tx * 8 + c];
#pragma unroll
            for (int r = 0; r < 4; r++)
#pragma unroll
                for (int c = 0; c < 8; c++) acc[r][c] = fmaf(xv[r], wv[c], acc[r][c]);
        }
        __syncthreads();
    }
#pragma unroll
    for (int r = 0; r < 4; r++) {
        int row = i0 + ty * 4 + r;
        float4 o0 = make_float4(acc[r][0], acc[r][1], acc[r][2], acc[r][3]);
        float4 o1 = make_float4(acc[r][4], acc[r][5], acc[r][6], acc[r][7]);
        *(float4*)&out[(size_t)row * F + tx * 8]     = o0;
        *(float4*)&out[(size_t)row * F + tx * 8 + 4] = o1;
    }
}

// ---------------- kernel 2: f1/f2 and exp tables ----------------
__global__ __launch_bounds__(256) void fe_kernel(const float* __restrict__ a0,
                                                 const float* __restrict__ a1) {
    const int layer = blockIdx.y;
    const float* a = layer ? a1 : a0;
    const int warp = threadIdx.x >> 5, lane = threadIdx.x & 31;
    const int i = blockIdx.x * 8 + warp;
    const float* wh = &g_Wh[layer][(size_t)i * F];

    float s1 = 0.f, s2 = 0.f;
#pragma unroll
    for (int m = 0; m < 4; m++) {
        int f = lane + 32 * m;
        float v = wh[f];
        s1 = fmaf(v, a[f], s1);
        s2 = fmaf(v, a[F + f], s2);
    }
#pragma unroll
    for (int o = 16; o; o >>= 1) {
        s1 += __shfl_xor_sync(0xffffffffu, s1, o);
        s2 += __shfl_xor_sync(0xffffffffu, s2, o);
    }
    if (lane == 0) {
        g_f1 [layer][i] = s1;
        g_f2 [layer][i] = s2;
        g_E1 [layer][i] = expf(s1);
        g_E1a[layer][i] = expf(ALPHA * s1);
        g_E2 [layer][i] = expf(s2);
        g_E2a[layer][i] = expf(ALPHA * s2);
    }
}

// ---------------- kernel 2b: pre-pack Wh into mma B fragments (bf16) ----------------
// For kstep ks (j0=16*ks), ftile pair fp, lane l:
//   fA = 16*fp + (l>>2), fB = fA + 8, j = j0 + (l&3)*2
//   b0 = pack(Wh[j][f], Wh[j+1][f]); b1 = pack(Wh[j+8][f], Wh[j+9][f])
__global__ __launch_bounds__(256) void bfrag_kernel() {
    const int gt = blockIdx.x * 256 + threadIdx.x;   // 0 .. 2*512*16*32-1
    const int lane = gt & 31;
    const int fp   = (gt >> 5) & 15;
    const int ks   = (gt >> 9) & 511;
    const int layer = gt >> 18;
    const int r = lane >> 2, qd = lane & 3;
    const int j0 = ks * 16 + qd * 2;
    const int fA = fp * 16 + r, fB = fA + 8;
    const float* Wh = g_Wh[layer];

    uint4 v;
    v.x = bf16pk(Wh[(size_t)j0 * F + fA],       Wh[(size_t)(j0 + 1) * F + fA]);
    v.y = bf16pk(Wh[(size_t)(j0 + 8) * F + fA], Wh[(size_t)(j0 + 9) * F + fA]);
    v.z = bf16pk(Wh[(size_t)j0 * F + fB],       Wh[(size_t)(j0 + 1) * F + fB]);
    v.w = bf16pk(Wh[(size_t)(j0 + 8) * F + fB], Wh[(size_t)(j0 + 9) * F + fB]);
    g_Bfrag[gt] = v;
}

// ---------------- kernel 3: HMMA fused masked-softmax attention ----------------
// Block = 128 rows; 8 warps; warp w owns rows i0+w*16 .. +15, all 128 features.
// P generated directly in A-fragment registers; B fragments pre-packed in gmem.
__global__ __launch_bounds__(256, 1) void attn_mma() {
    __shared__ __align__(16) float4 tab[CHUNK];      // (f2, E2, E2a, 0) per j, 16KB

    const int layer = blockIdx.y;
    const int i0 = blockIdx.x * 128;
    const int tid = threadIdx.x;
    const int w = tid >> 5, lane = tid & 31;
    const int r = lane >> 2, qd = lane & 3;
    const int rA = i0 + w * 16 + r, rB = rA + 8;

    const float f1A = g_f1[layer][rA], e1A = g_E1[layer][rA], e1aA = g_E1a[layer][rA];
    const float f1B = g_f1[layer][rB], e1B = g_E1[layer][rB], e1aB = g_E1a[layer][rB];
    const unsigned int* mA = g_mask + (size_t)layer * N * (N / 32) + (size_t)rA * (N / 32);
    const unsigned int* mB = g_mask + (size_t)layer * N * (N / 32) + (size_t)rB * (N / 32);
    const uint4* __restrict__ bfb = g_Bfrag + ((size_t)layer * 512) * 16 * 32 + lane;

    float acc[16][4];
#pragma unroll
    for (int nt = 0; nt < 16; nt++)
#pragma unroll
        for (int q = 0; q < 4; q++) acc[nt][q] = 0.f;
    float zA = 0.f, zB = 0.f;

    for (int c = 0; c < N / CHUNK; c++) {
        __syncthreads();
        {
            const float* F2  = g_f2 [layer] + c * CHUNK;
            const float* E2  = g_E2 [layer] + c * CHUNK;
            const float* E2a = g_E2a[layer] + c * CHUNK;
            for (int t = tid; t < CHUNK; t += 256)
                tab[t] = make_float4(F2[t], E2[t], E2a[t], 0.f);
        }
        __syncthreads();

        unsigned int mwA = 0u, mwB = 0u;
#pragma unroll 4
        for (int ks = 0; ks < CHUNK / 16; ks++) {
            if (!(ks & 1)) {
                int widx = c * (CHUNK / 32) + (ks >> 1);
                mwA = mA[widx];
                mwB = mB[widx];
            }
            const int sh = (ks & 1) * 16;
            const int jt = ks * 16 + qd * 2;

            // B fragments: 8 coalesced uint4 loads (16 n-tiles)
            uint4 Bv[8];
            const uint4* bp = bfb + ((size_t)(c * (CHUNK / 16) + ks) * 16) * 32;
#pragma unroll
            for (int fp = 0; fp < 8; fp++) Bv[fp] = __ldg(bp + fp * 32);

            // A fragments: 8 P values computed in-place
            float4 T0 = tab[jt], T1 = tab[jt + 1], T8 = tab[jt + 8], T9 = tab[jt + 9];
            float pA0 = pval(f1A, e1A, e1aA, T0, mwA, sh + qd * 2);
            float pA1 = pval(f1A, e1A, e1aA, T1, mwA, sh + qd * 2 + 1);
            float pA8 = pval(f1A, e1A, e1aA, T8, mwA, sh + qd * 2 + 8);
            float pA9 = pval(f1A, e1A, e1aA, T9, mwA, sh + qd * 2 + 9);
            float pB0 = pval(f1B, e1B, e1aB, T0, mwB, sh + qd * 2);
            float pB1 = pval(f1B, e1B, e1aB, T1, mwB, sh + qd * 2 + 1);
            float pB8 = pval(f1B, e1B, e1aB, T8, mwB, sh + qd * 2 + 8);
            float pB9 = pval(f1B, e1B, e1aB, T9, mwB, sh + qd * 2 + 9);
            zA += (pA0 + pA1) + (pA8 + pA9);
            zB += (pB0 + pB1) + (pB8 + pB9);

            uint32_t A[4];
            A[0] = bf16pk(pA0, pA1);   // row rA, k 0-7 slot
            A[1] = bf16pk(pB0, pB1);   // row rB (groupID+8), k 0-7
            A[2] = bf16pk(pA8, pA9);   // row rA, k 8-15
            A[3] = bf16pk(pB8, pB9);   // row rB, k 8-15

#pragma unroll
            for (int nt = 0; nt < 16; nt++) {
                const uint32_t* bb = ((const uint32_t*)&Bv[nt >> 1]) + (nt & 1) * 2;
                mma16816(acc[nt], A, bb);
            }
        }
    }

    // Z reduce within quad (4 lanes share a row)
    zA += __shfl_xor_sync(0xffffffffu, zA, 1);
    zA += __shfl_xor_sync(0xffffffffu, zA, 2);
    zB += __shfl_xor_sync(0xffffffffu, zB, 1);
    zB += __shfl_xor_sync(0xffffffffu, zB, 2);
    const float izA = 1.f / zA, izB = 1.f / zB;

    float* HA = &g_H[layer][(size_t)rA * F];
    float* HB = &g_H[layer][(size_t)rB * F];
#pragma unroll
    for (int nt = 0; nt < 16; nt++) {
        int col = nt * 8 + qd * 2;
        *(float2*)(HA + col) = make_float2(acc[nt][0] * izA, acc[nt][1] * izA);
        *(float2*)(HB + col) = make_float2(acc[nt][2] * izB, acc[nt][3] * izB);
    }
}

// ---------------- kernel 4: layernorm(query) -> g_q ----------------
__global__ void qnorm_kernel(const float* __restrict__ query,
                             const float* __restrict__ gamma,
                             const float* __restrict__ beta) {
    __shared__ float red[4];
    const int t = threadIdx.x;  // 128 threads
    float x = query[t];
    float s = x;
#pragma unroll
    for (int o = 16; o; o >>= 1) s += __shfl_xor_sync(0xffffffffu, s, o);
    if ((t & 31) == 0) red[t >> 5] = s;
    __syncthreads();
    float mu = (red[0] + red[1] + red[2] + red[3]) * (1.f / 128.f);
    float d = x - mu;
    float v = d * d;
    __syncthreads();
#pragma unroll
    for (int o = 16; o; o >>= 1) v += __shfl_xor_sync(0xffffffffu, v, o);
    if ((t & 31) == 0) red[t >> 5] = v;
    __syncthreads();
    float var = (red[0] + red[1] + red[2] + red[3]) * (1.f / 128.f);
    g_q[t] = d * rsqrtf(var + 1e-5f) * gamma[t] + beta[t];
}

// ---------------- kernel 5: score softmax + mix + residual ----------------
__global__ __launch_bounds__(256) void mix_kernel(const float* __restrict__ input_hs,
                                                  const float* __restrict__ M,
                                                  const float* __restrict__ resp,
                                                  float* __restrict__ out) {
    const int warp = threadIdx.x >> 5, lane = threadIdx.x & 31;
    const int i = blockIdx.x * 8 + warp;
    const float* h0 = &g_H[0][(size_t)i * F];
    const float* h1 = &g_H[1][(size_t)i * F];
    const float* mm = &M[(size_t)i * F];
    const float* x0 = &input_hs[(size_t)i * F];

    float h0v[4], h1v[4], mv[4];
    float d0 = 0.f, d1 = 0.f, d2 = 0.f;
#pragma unroll
    for (int m = 0; m < 4; m++) {
        int f = lane + 32 * m;
        h0v[m] = h0[f];
        h1v[m] = h1[f];
        mv[m]  = mm[f];
        float q = g_q[f];
        d0 = fmaf(h0v[m], q, d0);
        d1 = fmaf(h1v[m], q, d1);
        d2 = fmaf(mv[m],  q, d2);
    }
#pragma unroll
    for (int o = 16; o; o >>= 1) {
        d0 += __shfl_xor_sync(0xffffffffu, d0, o);
        d1 += __shfl_xor_sync(0xffffffffu, d1, o);
        d2 += __shfl_xor_sync(0xffffffffu, d2, o);
    }
    float mx = fmaxf(d0, fmaxf(d1, d2));
    float e0 = expf(d0 - mx), e1 = expf(d1 - mx), e2 = expf(d2 - mx);
    float inv = 1.f / (e0 + e1 + e2);
    float s0 = e0 * inv, s1 = e1 * inv, s2 = e2 * inv;
    float r = resp[0];
#pragma unroll
    for (int m = 0; m < 4; m++) {
        int f = lane + 32 * m;
        out[(size_t)i * F + f] = fmaf(r, s0 * h0v[m] + s1 * h1v[m] + s2 * mv[m], x0[f]);
    }
}

// ---------------- launcher ----------------
extern "C" void kernel_launch(void* const* d_in, const int* in_sizes, int n_in,
                              void* d_out, int out_size) {
    const float* input_hs = (const float*)d_in[0];
    const void*  adjs     = d_in[1];
    const float* MPNN     = (const float*)d_in[2];
    const float* query    = (const float*)d_in[3];
    const float* W0       = (const float*)d_in[4];
    const float* a0       = (const float*)d_in[5];
    const float* W1       = (const float*)d_in[6];
    const float* a1       = (const float*)d_in[7];
    const float* gamma    = (const float*)d_in[8];
    const float* beta     = (const float*)d_in[9];
    const float* res      = (const float*)d_in[10];
    float* out = (float*)d_out;

    detect_kernel<<<1, 256>>>((const unsigned int*)adjs);
    repack_kernel<<<(2 * (size_t)N * N / 32) / 256, 256>>>(adjs);
    wh_kernel   <<<dim3(N / 64, 2), 256>>>(input_hs, W0, W1);
    fe_kernel   <<<dim3(N / 8, 2), 256>>>(a0, a1);
    bfrag_kernel<<<2 * 512 * 16 * 32 / 256, 256>>>();
    attn_mma    <<<dim3(N / 128, 2), 256>>>();
    qnorm_kernel<<<1, 128>>>(query, gamma, beta);
    mix_kernel  <<<N / 8, 256>>>(input_hs, MPNN, res, out);
}